// round 8
// baseline (speedup 1.0000x reference)
#include <cuda_runtime.h>
#include <cuda_bf16.h>
#include <cstdint>

// Problem shape (fixed by dataset)
#define BB 64
#define LL 256
#define TT 1600
#define TC 32                       // time-chunk (= halo width)
#define SROW 33                     // smem row stride (floats), conflict-free
#define NCH 50                      // TT / TC
#define NBUF 4                      // pipeline depth
#define BUF_FLOATS (LL * SROW)      // 8448
#define SMEM_BYTES (NBUF * BUF_FLOATS * 4)   // 135,168 B
#define LN2 0.69314718055994531f
// Sentinel in LOG2 domain: NEG/ln2, so that sentinel*ln2 == -1e30 (reference NEG)
#define NEGV2 (-1.4426950408889634e30f)

__device__ float g_alpha_last[BB];
__device__ unsigned int g_done_ctr = 0;

__device__ __forceinline__ float f_ex2(float x) {
    float r; asm("ex2.approx.f32 %0, %1;" : "=f"(r) : "f"(x)); return r;
}
__device__ __forceinline__ float f_lg2(float x) {
    float r; asm("lg2.approx.f32 %0, %1;" : "=f"(r) : "f"(x)); return r;
}

// log2-domain logaddexp + lp2 (zero FMULs; 2 MUFU)
__device__ __forceinline__ float lae2_add(float x, float y, float lp)
{
    float m = fmaxf(x, y);
    float d = fminf(x, y) - m;          // <= 0; ex2 underflows to 0 safely
    float s = m + lp;                   // off the MUFU chain
    return s + f_lg2(1.0f + f_ex2(d));
}

__device__ __forceinline__ void mbar_init(uint32_t a, uint32_t cnt) {
    asm volatile("mbarrier.init.shared.b64 [%0], %1;" :: "r"(a), "r"(cnt) : "memory");
}
__device__ __forceinline__ void mbar_arrive(uint32_t a) {
    asm volatile("mbarrier.arrive.shared.b64 _, [%0];" :: "r"(a) : "memory");
}
__device__ __forceinline__ void mbar_wait(uint32_t a, uint32_t phase) {
    asm volatile(
        "{\n\t.reg .pred P;\n\t"
        "WL_%=:\n\t"
        "mbarrier.try_wait.parity.acquire.cta.shared::cta.b64 P, [%0], %1, 0x989680;\n\t"
        "@P bra.uni WD_%=;\n\t"
        "bra.uni WL_%=;\n\t"
        "WD_%=:\n\t}"
        :: "r"(a), "r"(phase) : "memory");
}

extern __shared__ float sbuf[];         // NBUF buffers of [LL][SROW]

// ---------------------------------------------------------------------------
// One block per batch, 512 threads.
//   warps 0-3  (recursion): halo layout — warp w carries labels [64w-32,64w+64),
//     3 slots/thread, log2-domain alpha, exact owned region for 32 steps.
//     Halo refresh at chunk boundary via bar.sync 1,128 (recursion-only).
//     Steps run UNCONDITIONALLY; alpha(tgt_t,tgt_l) snapshot at t==tgt_t.
//   warps 4-15 (convert): LDG.128 raw probs chunk -> lg2 -> STS (smem, log2) +
//     STG (gmem, *ln2 = natural log output). Producer/consumer via mbarrier
//     ring, depth 4 — convert runs ahead; recursion paced by its own chain.
// ---------------------------------------------------------------------------
__global__ void __launch_bounds__(512, 1)
k_mdn(const float* __restrict__ probs,
      const int* __restrict__ text_lengths,
      const int* __restrict__ mel_lengths,
      float* __restrict__ out)
{
    __shared__ float hbuf[2][4][32];
    __shared__ __align__(8) unsigned long long mbar_store[2 * NBUF];

    const int b    = blockIdx.x;
    const int tid  = threadIdx.x;
    const int warp = tid >> 5;
    const int lane = tid & 31;

    const int tgt_t = __ldg(mel_lengths  + b) - 1;
    const int tgt_l = __ldg(text_lengths + b) - 1;

    const float* pbase = probs + (size_t)b * LL * TT;
    float*       obase = out + 1 + (size_t)b * LL * TT;

    const uint32_t mb = (uint32_t)__cvta_generic_to_shared(mbar_store);
#define FULL_A(s)  (mb + (uint32_t)(s) * 8u)
#define EMPTY_A(s) (mb + 32u + (uint32_t)(s) * 8u)

    if (tid == 0) {
#pragma unroll
        for (int s = 0; s < NBUF; ++s) {
            mbar_init(FULL_A(s), 12);   // one arrive per convert warp
            mbar_init(EMPTY_A(s), 4);   // one arrive per recursion warp
        }
    }
    __syncthreads();

    if (warp >= 4) {
        // ======================= convert / producer =======================
        const int wtid = tid - 128;     // 0..383
        for (int c = 0; c < NCH; ++c) {
            const int s = c & 3, u = c >> 2;
            mbar_wait(EMPTY_A(s), (u & 1) ^ 1);   // first use passes immediately
            float* buf = sbuf + s * BUF_FLOATS;
            const int t0 = c * TC;
            for (int i = wtid; i < (LL * TC) / 4; i += 384) {
                const int row = i >> 3, c4 = (i & 7) * 4;
                const float4 v = *reinterpret_cast<const float4*>(
                                     pbase + (size_t)row * TT + t0 + c4);
                float l0 = f_lg2(v.x + 1e-30f);
                float l1 = f_lg2(v.y + 1e-30f);
                float l2 = f_lg2(v.z + 1e-30f);
                float l3 = f_lg2(v.w + 1e-30f);
                float* sp = buf + row * SROW + c4;
                sp[0] = l0; sp[1] = l1; sp[2] = l2; sp[3] = l3;
                float* gp = obase + (size_t)row * TT + t0 + c4;   // 4B-aligned
                gp[0] = l0 * LN2; gp[1] = l1 * LN2;
                gp[2] = l2 * LN2; gp[3] = l3 * LN2;
            }
            if (lane == 0) mbar_arrive(FULL_A(s));
        }
    } else {
        // ======================= recursion / consumer =======================
        const int Wb = 64 * warp - 32;
        const int r0 = Wb + 3 * lane, r1 = r0 + 1, r2 = r0 + 2;
        const bool v0 = (r0 >= 0), v1 = (r1 >= 0), v2 = (r2 >= 0);
        const int cr0 = (v0 ? r0 : 0) * SROW;
        const int cr1 = (v1 ? r1 : 0) * SROW;
        const int cr2 = (v2 ? r2 : 0) * SROW;

        // snapshot target: owned slot of label tgt_l
        const int wt   = tgt_l >> 6;
        const int slot = (tgt_l & 63) + 32;
        const bool mine = (warp == wt) && (lane == slot / 3);
        const int  msel = slot - 3 * (slot / 3);        // 0,1,2

        float a0 = NEGV2, a1 = NEGV2, a2 = NEGV2;

#define STEP(BUFC, J)                                                     \
        {                                                                 \
            float lp0 = (BUFC)[cr0 + (J)];                                \
            float lp1 = (BUFC)[cr1 + (J)];                                \
            float lp2 = (BUFC)[cr2 + (J)];                                \
            float sh   = __shfl_up_sync(0xffffffffu, a2, 1);              \
            float left = (lane == 0) ? NEGV2 : sh;                        \
            float n0 = lae2_add(a0, left, lp0);                           \
            float n1 = lae2_add(a1, a0,   lp1);                           \
            float n2 = lae2_add(a2, a1,   lp2);                           \
            a0 = v0 ? n0 : NEGV2;                                         \
            a1 = v1 ? n1 : NEGV2;                                         \
            a2 = v2 ? n2 : NEGV2;                                         \
        }

#define HALO(C)                                                           \
        {                                                                 \
            const int s0 = 3 * lane;                                      \
            float* hw = &hbuf[(C) & 1][warp][0];                          \
            if (s0     >= 64) hw[s0 - 64] = a0;                           \
            if (s0 + 1 >= 64) hw[s0 - 63] = a1;                           \
            if (s0 + 2 >= 64) hw[s0 - 62] = a2;                           \
            asm volatile("bar.sync 1, 128;" ::: "memory");                \
            if (warp > 0) {                                               \
                const float* hr = &hbuf[(C) & 1][warp - 1][0];            \
                if (s0     < 32) a0 = hr[s0];                             \
                if (s0 + 1 < 32) a1 = hr[s0 + 1];                         \
                if (s0 + 2 < 32) a2 = hr[s0 + 2];                         \
            }                                                             \
        }

        // ---- chunk 0 (peeled: t=0 is init, steps t=1..31) ----
        mbar_wait(FULL_A(0), 0);
        {
            const float* bufc = sbuf;
            if (warp == 0 && lane == 10) a2 = bufc[0];   // alpha[0][0] (log2)
            if (tgt_t == 0 && mine)
                g_alpha_last[b] = ((msel == 0) ? a0 : (msel == 1) ? a1 : a2) * LN2;
#pragma unroll
            for (int j = 1; j < TC; ++j) {
                STEP(bufc, j);
                if (mine && j == tgt_t)
                    g_alpha_last[b] = ((msel == 0) ? a0 : (msel == 1) ? a1 : a2) * LN2;
            }
        }
        if (lane == 0) mbar_arrive(EMPTY_A(0));
        HALO(0)

        // ---- chunks 1..49 ----
        for (int c = 1; c < NCH; ++c) {
            const int s = c & 3, u = c >> 2;
            mbar_wait(FULL_A(s), u & 1);
            const float* bufc = sbuf + s * BUF_FLOATS;
            const int tbase = c * TC;
#pragma unroll
            for (int j = 0; j < TC; ++j) {
                STEP(bufc, j);
                if (mine && (tbase + j) == tgt_t)
                    g_alpha_last[b] = ((msel == 0) ? a0 : (msel == 1) ? a1 : a2) * LN2;
            }
            if (lane == 0) mbar_arrive(EMPTY_A(s));
            HALO(c)
        }
    }

    __syncthreads();

    // last block to finish computes loss = -mean(alpha_last)
    if (tid == 0) {
        __threadfence();
        unsigned old = atomicAdd(&g_done_ctr, 1u);
        if (old == BB - 1) {
            g_done_ctr = 0;                          // reset for graph replay
            __threadfence();
            float s = 0.0f;
#pragma unroll
            for (int i = 0; i < BB; ++i) s += g_alpha_last[i];
            out[0] = -s * (1.0f / BB);
        }
    }
}

// ---------------------------------------------------------------------------
extern "C" void kernel_launch(void* const* d_in, const int* in_sizes, int n_in,
                              void* d_out, int out_size)
{
    const float* probs        = (const float*)d_in[0];
    // d_in[1] = melspec (unused by the computation)
    const int*   text_lengths = (const int*)d_in[2];
    const int*   mel_lengths  = (const int*)d_in[3];

    float* out = (float*)d_out;   // out[0] = loss, out[1..] = log matrix

    static bool attr_set = false;
    if (!attr_set) {
        cudaFuncSetAttribute(k_mdn, cudaFuncAttributeMaxDynamicSharedMemorySize,
                             SMEM_BYTES);
        attr_set = true;
    }
    k_mdn<<<BB, 512, SMEM_BYTES>>>(probs, text_lengths, mel_lengths, out);
    (void)in_sizes; (void)n_in; (void)out_size;
}

// round 9
// speedup vs baseline: 1.2966x; 1.2966x over previous
#include <cuda_runtime.h>
#include <cuda_bf16.h>
#include <cstdint>

// Problem shape (fixed by dataset)
#define BB 64
#define LL 256
#define TT 1600
#define TC 32                       // time-chunk (= halo width)
#define SROW 33                     // smem row stride (floats), conflict-free
#define NCH 50                      // TT / TC
#define NBUF 4                      // pipeline depth (power of 2)
#define BUF_FLOATS ((LL + 1) * SROW)        // 8481 (row 256 = sentinel lp row)
#define SMEM_BYTES (NBUF * BUF_FLOATS * 4)  // 135,696 B
#define LN2 0.69314718055994531f
// Sentinel in LOG2 domain: NEG/ln2, so sentinel*ln2 == -1e30 (reference NEG)
#define NEGV2 (-1.4426950408889634e30f)

__device__ float g_alpha_last[BB];
__device__ unsigned int g_done_ctr = 0;

__device__ __forceinline__ float f_ex2(float x) {
    float r; asm("ex2.approx.f32 %0, %1;" : "=f"(r) : "f"(x)); return r;
}
__device__ __forceinline__ float f_lg2(float x) {
    float r; asm("lg2.approx.f32 %0, %1;" : "=f"(r) : "f"(x)); return r;
}

// log2-domain logaddexp + lp2 (2 MUFU, no FMUL)
__device__ __forceinline__ float lae2_add(float x, float y, float lp)
{
    float m = fmaxf(x, y);
    float d = fminf(x, y) - m;          // <= 0; ex2 underflows to 0 safely
    float s = m + lp;                   // off the MUFU chain
    return s + f_lg2(1.0f + f_ex2(d));
}

__device__ __forceinline__ void mbar_init(uint32_t a, uint32_t cnt) {
    asm volatile("mbarrier.init.shared.b64 [%0], %1;" :: "r"(a), "r"(cnt) : "memory");
}
__device__ __forceinline__ void mbar_arrive(uint32_t a) {
    asm volatile("mbarrier.arrive.shared.b64 _, [%0];" :: "r"(a) : "memory");
}
__device__ __forceinline__ void mbar_wait(uint32_t a, uint32_t phase) {
    asm volatile(
        "{\n\t.reg .pred P;\n\t"
        "WL_%=:\n\t"
        "mbarrier.try_wait.parity.acquire.cta.shared::cta.b64 P, [%0], %1, 0x989680;\n\t"
        "@P bra.uni WD_%=;\n\t"
        "bra.uni WL_%=;\n\t"
        "WD_%=:\n\t}"
        :: "r"(a), "r"(phase) : "memory");
}

extern __shared__ float sbuf[];         // NBUF buffers of [(LL+1)][SROW]

// ---------------------------------------------------------------------------
// Recursion kernel: one block per batch, 256 threads.
//   warps 0-3 (recursion): halo layout — warp w carries labels [64w-32,64w+64),
//     3 slots/thread, log2-domain alpha. Out-of-range slots self-pin via the
//     sentinel lp row (row 256 = NEGV2) — no per-step SELs. Halo refresh at
//     chunk boundary via bar.sync 1,128. Unconditional steps + snapshot.
//   warps 4-7 (convert): LDG.128 raw probs (16 float4/thread, unrolled for
//     MLP) -> lg2 -> scalar STS into padded ring. NO gmem stores (the output
//     matrix is produced by the overlapped k_elem on another stream).
// ---------------------------------------------------------------------------
__global__ void __launch_bounds__(256, 1)
k_rec(const float* __restrict__ probs,
      const int* __restrict__ text_lengths,
      const int* __restrict__ mel_lengths,
      float* __restrict__ out)
{
    __shared__ float hbuf[2][4][32];
    __shared__ __align__(8) unsigned long long mbar_store[2 * NBUF];

    const int b    = blockIdx.x;
    const int tid  = threadIdx.x;
    const int warp = tid >> 5;
    const int lane = tid & 31;

    const int tgt_t = __ldg(mel_lengths  + b) - 1;
    const int tgt_l = __ldg(text_lengths + b) - 1;

    const float* pbase = probs + (size_t)b * LL * TT;

    const uint32_t mb = (uint32_t)__cvta_generic_to_shared(mbar_store);
#define FULL_A(s)  (mb + (uint32_t)(s) * 8u)
#define EMPTY_A(s) (mb + 32u + (uint32_t)(s) * 8u)

    if (tid == 0) {
#pragma unroll
        for (int s = 0; s < NBUF; ++s) {
            mbar_init(FULL_A(s), 4);    // one arrive per convert warp
            mbar_init(EMPTY_A(s), 4);   // one arrive per recursion warp
        }
    }
    // sentinel lp row (row LL) of every buffer = NEGV2, set once
    if (tid < SROW) {
#pragma unroll
        for (int s = 0; s < NBUF; ++s)
            sbuf[s * BUF_FLOATS + LL * SROW + tid] = NEGV2;
    }
    __syncthreads();

    if (warp >= 4) {
        // ======================= convert / producer =======================
        const int wtid = tid - 128;     // 0..127
        for (int c = 0; c < NCH; ++c) {
            const int s = c & 3, u = c >> 2;
            mbar_wait(EMPTY_A(s), (u & 1) ^ 1);   // first use passes immediately
            float* buf = sbuf + s * BUF_FLOATS;
            const float* gsrc = pbase + c * TC;
#pragma unroll
            for (int k = 0; k < 16; ++k) {
                const int i   = wtid + k * 128;    // 0..2047
                const int row = i >> 3;            // 8 float4 per 32-float row
                const int c4  = (i & 7) * 4;
                const float4 v = *reinterpret_cast<const float4*>(
                                     gsrc + (size_t)row * TT + c4);
                float* sp = buf + row * SROW + c4;
                sp[0] = f_lg2(v.x + 1e-30f);
                sp[1] = f_lg2(v.y + 1e-30f);
                sp[2] = f_lg2(v.z + 1e-30f);
                sp[3] = f_lg2(v.w + 1e-30f);
            }
            if (lane == 0) mbar_arrive(FULL_A(s));
        }
    } else {
        // ======================= recursion / consumer =======================
        const int Wb = 64 * warp - 32;
        const int r0 = Wb + 3 * lane, r1 = r0 + 1, r2 = r0 + 2;
        // invalid (label<0) slots read the sentinel lp row -> self-pinned
        const int cr0 = ((r0 >= 0) ? r0 : LL) * SROW;
        const int cr1 = ((r1 >= 0) ? r1 : LL) * SROW;
        const int cr2 = ((r2 >= 0) ? r2 : LL) * SROW;

        // snapshot target: owned slot of label tgt_l
        const int wt   = tgt_l >> 6;
        const int slot = (tgt_l & 63) + 32;
        const bool mine = (warp == wt) && (lane == slot / 3);
        const int  msel = slot - 3 * (slot / 3);        // 0,1,2

        float a0 = NEGV2, a1 = NEGV2, a2 = NEGV2;

#define STEP(BUFC, J)                                                     \
        {                                                                 \
            float lp0 = (BUFC)[cr0 + (J)];                                \
            float lp1 = (BUFC)[cr1 + (J)];                                \
            float lp2 = (BUFC)[cr2 + (J)];                                \
            float sh   = __shfl_up_sync(0xffffffffu, a2, 1);              \
            float left = (lane == 0) ? NEGV2 : sh;                        \
            float n0 = lae2_add(a0, left, lp0);                           \
            float n1 = lae2_add(a1, a0,   lp1);                           \
            float n2 = lae2_add(a2, a1,   lp2);                           \
            a0 = n0; a1 = n1; a2 = n2;                                    \
        }

#define HALO(C)                                                           \
        {                                                                 \
            const int s0 = 3 * lane;                                      \
            float* hw = &hbuf[(C) & 1][warp][0];                          \
            if (s0     >= 64) hw[s0 - 64] = a0;                           \
            if (s0 + 1 >= 64) hw[s0 - 63] = a1;                           \
            if (s0 + 2 >= 64) hw[s0 - 62] = a2;                           \
            asm volatile("bar.sync 1, 128;" ::: "memory");                \
            if (warp > 0) {                                               \
                const float* hr = &hbuf[(C) & 1][warp - 1][0];            \
                if (s0     < 32) a0 = hr[s0];                             \
                if (s0 + 1 < 32) a1 = hr[s0 + 1];                         \
                if (s0 + 2 < 32) a2 = hr[s0 + 2];                         \
            }                                                             \
        }

        // ---- chunk 0 (peeled: t=0 is init, steps t=1..31) ----
        mbar_wait(FULL_A(0), 0);
        {
            const float* bufc = sbuf;
            if (warp == 0 && lane == 10) a2 = bufc[0];   // alpha[0][0] (log2)
            if (tgt_t == 0 && mine)
                g_alpha_last[b] = ((msel == 0) ? a0 : (msel == 1) ? a1 : a2) * LN2;
#pragma unroll
            for (int j = 1; j < TC; ++j) {
                STEP(bufc, j);
                if (mine && j == tgt_t)
                    g_alpha_last[b] = ((msel == 0) ? a0 : (msel == 1) ? a1 : a2) * LN2;
            }
        }
        if (lane == 0) mbar_arrive(EMPTY_A(0));
        HALO(0)

        // ---- chunks 1..49 ----
        for (int c = 1; c < NCH; ++c) {
            const int s = c & 3, u = c >> 2;
            mbar_wait(FULL_A(s), u & 1);
            const float* bufc = sbuf + s * BUF_FLOATS;
            const int tbase = c * TC;
#pragma unroll
            for (int j = 0; j < TC; ++j) {
                STEP(bufc, j);
                if (mine && (tbase + j) == tgt_t)
                    g_alpha_last[b] = ((msel == 0) ? a0 : (msel == 1) ? a1 : a2) * LN2;
            }
            if (lane == 0) mbar_arrive(EMPTY_A(s));
            HALO(c)
        }
    }

    __syncthreads();

    // last block to finish computes loss = -mean(alpha_last)
    if (tid == 0) {
        __threadfence();
        unsigned old = atomicAdd(&g_done_ctr, 1u);
        if (old == BB - 1) {
            g_done_ctr = 0;                          // reset for graph replay
            __threadfence();
            float s = 0.0f;
#pragma unroll
            for (int i = 0; i < BB; ++i) s += g_alpha_last[i];
            out[0] = -s * (1.0f / BB);
        }
    }
}

// ---------------------------------------------------------------------------
// Elementwise kernel (runs on a forked stream, fills the idle SMs):
// out[1 + i] = log(probs[i] + 1e-30)
// ---------------------------------------------------------------------------
__global__ void k_elem(const float* __restrict__ probs,
                       float* __restrict__ mat,     // = out + 1
                       long long nvec)              // number of float4
{
    long long i = (long long)blockIdx.x * blockDim.x + threadIdx.x;
    long long stride = (long long)gridDim.x * blockDim.x;
    const float4* p4 = reinterpret_cast<const float4*>(probs);
    for (; i < nvec; i += stride) {
        float4 v = p4[i];
        long long o = i * 4;
        mat[o + 0] = __logf(v.x + 1e-30f);
        mat[o + 1] = __logf(v.y + 1e-30f);
        mat[o + 2] = __logf(v.z + 1e-30f);
        mat[o + 3] = __logf(v.w + 1e-30f);
    }
}

// ---------------------------------------------------------------------------
extern "C" void kernel_launch(void* const* d_in, const int* in_sizes, int n_in,
                              void* d_out, int out_size)
{
    const float* probs        = (const float*)d_in[0];
    // d_in[1] = melspec (unused by the computation)
    const int*   text_lengths = (const int*)d_in[2];
    const int*   mel_lengths  = (const int*)d_in[3];

    float* out = (float*)d_out;   // out[0] = loss, out[1..] = log matrix

    static cudaStream_t s2 = nullptr;
    static cudaEvent_t  evF = nullptr, evJ = nullptr;
    if (s2 == nullptr) {
        cudaStreamCreateWithFlags(&s2, cudaStreamNonBlocking);
        cudaEventCreateWithFlags(&evF, cudaEventDisableTiming);
        cudaEventCreateWithFlags(&evJ, cudaEventDisableTiming);
        cudaFuncSetAttribute(k_rec, cudaFuncAttributeMaxDynamicSharedMemorySize,
                             SMEM_BYTES);
    }

    const long long nvec = (long long)BB * LL * TT / 4;

    // fork: elementwise on s2, recursion on the main (capture) stream
    cudaEventRecord(evF, 0);
    cudaStreamWaitEvent(s2, evF, 0);
    k_elem<<<1184, 256, 0, s2>>>(probs, out + 1, nvec);
    cudaEventRecord(evJ, s2);

    k_rec<<<BB, 256, SMEM_BYTES, 0>>>(probs, text_lengths, mel_lengths, out);

    // join
    cudaStreamWaitEvent(0, evJ, 0);
    (void)in_sizes; (void)n_in; (void)out_size;
}

// round 10
// speedup vs baseline: 1.5641x; 1.2063x over previous
#include <cuda_runtime.h>
#include <cuda_bf16.h>
#include <cstdint>

// Problem shape (fixed by dataset)
#define BB 64
#define LL 256
#define TT 1600
#define TC 32                       // time-chunk (= halo width)
#define SROW 33                     // smem row stride (floats), conflict-free
#define NCH 50                      // TT / TC
#define NBUF 4                      // pipeline depth
#define BUF_FLOATS (LL * SROW)      // 8448
#define SMEM_BYTES (NBUF * BUF_FLOATS * 4)   // 135,168 B
#define LN2 0.69314718055994531f
#define E_SENT (-(1 << 26))         // exponent sentinel (int)

__device__ float g_alpha_last[BB];
__device__ unsigned int g_done_ctr = 0;

__device__ __forceinline__ float f_lg2(float x) {
    float r; asm("lg2.approx.f32 %0, %1;" : "=f"(r) : "f"(x)); return r;
}
// 2^k as float, clamped: k>126 -> 2^126, k<-126 -> 0
__device__ __forceinline__ float pow2s(int k) {
    k = (k > 126) ? 126 : k;
    return (k < -126) ? 0.0f : __int_as_float((k + 127) << 23);
}

__device__ __forceinline__ void mbar_init(uint32_t a, uint32_t cnt) {
    asm volatile("mbarrier.init.shared.b64 [%0], %1;" :: "r"(a), "r"(cnt) : "memory");
}
__device__ __forceinline__ void mbar_arrive(uint32_t a) {
    asm volatile("mbarrier.arrive.shared.b64 _, [%0];" :: "r"(a) : "memory");
}
__device__ __forceinline__ void mbar_wait(uint32_t a, uint32_t phase) {
    asm volatile(
        "{\n\t.reg .pred P;\n\t"
        "WL_%=:\n\t"
        "mbarrier.try_wait.parity.acquire.cta.shared::cta.b64 P, [%0], %1, 0x989680;\n\t"
        "@P bra.uni WD_%=;\n\t"
        "bra.uni WL_%=;\n\t"
        "WD_%=:\n\t}"
        :: "r"(a), "r"(phase) : "memory");
}

extern __shared__ float sbuf[];         // NBUF buffers of [LL][SROW], RAW probs

// ---------------------------------------------------------------------------
// Recursion kernel: one block per batch, 256 threads.
//   warps 0-3 (recursion): halo layout (warp w carries labels [64w-32,64w+64),
//     3 slots/thread). Alpha in LINEAR domain as a*2^E (block floating point):
//     step = 1 FFMA chain, no MUFU. Renormalize every 16 steps: mantissa
//     normalize + sentinel scale adoption (segmented shfl scan) + pairwise
//     rebase; f = 2^(E_left - E_self) constant between renorms.
//     a == 0 represents the reference's absorbed -1e30 sentinel exactly.
//   warps 4-7 (convert): LDG.128 raw probs -> STS (raw copy, no math).
// ---------------------------------------------------------------------------
__global__ void __launch_bounds__(256, 1)
k_rec(const float* __restrict__ probs,
      const int* __restrict__ text_lengths,
      const int* __restrict__ mel_lengths,
      float* __restrict__ out)
{
    __shared__ float hA[2][4][32];      // halo exchange: mantissas
    __shared__ int   hE[2][4][32];      // halo exchange: exponents
    __shared__ __align__(8) unsigned long long mbar_store[2 * NBUF];

    const int b    = blockIdx.x;
    const int tid  = threadIdx.x;
    const int warp = tid >> 5;
    const int lane = tid & 31;

    const int tgt_t = __ldg(mel_lengths  + b) - 1;
    const int tgt_l = __ldg(text_lengths + b) - 1;

    const float* pbase = probs + (size_t)b * LL * TT;

    const uint32_t mb = (uint32_t)__cvta_generic_to_shared(mbar_store);
#define FULL_A(s)  (mb + (uint32_t)(s) * 8u)
#define EMPTY_A(s) (mb + 32u + (uint32_t)(s) * 8u)

    if (tid == 0) {
#pragma unroll
        for (int s = 0; s < NBUF; ++s) {
            mbar_init(FULL_A(s), 4);    // one arrive per convert warp
            mbar_init(EMPTY_A(s), 4);   // one arrive per recursion warp
        }
    }
    __syncthreads();

    if (warp >= 4) {
        // ======================= convert / producer (raw copy) =============
        const int wtid = tid - 128;     // 0..127
        for (int c = 0; c < NCH; ++c) {
            const int s = c & 3, u = c >> 2;
            mbar_wait(EMPTY_A(s), (u & 1) ^ 1);
            float* buf = sbuf + s * BUF_FLOATS;
            const float* gsrc = pbase + c * TC;
#pragma unroll
            for (int k = 0; k < 16; ++k) {
                const int i   = wtid + k * 128;    // 0..2047
                const int row = i >> 3;
                const int c4  = (i & 7) * 4;
                const float4 v = *reinterpret_cast<const float4*>(
                                     gsrc + (size_t)row * TT + c4);
                float* sp = buf + row * SROW + c4;
                sp[0] = v.x; sp[1] = v.y; sp[2] = v.z; sp[3] = v.w;
            }
            if (lane == 0) mbar_arrive(FULL_A(s));
        }
    } else {
        // ======================= recursion / consumer ======================
        const int Wb = 64 * warp - 32;
        const int r0 = Wb + 3 * lane, r1 = r0 + 1, r2 = r0 + 2;
        const int cr0 = ((r0 >= 0) ? r0 : 0) * SROW;   // invalid slots keep a=0
        const int cr1 = ((r1 >= 0) ? r1 : 0) * SROW;
        const int cr2 = ((r2 >= 0) ? r2 : 0) * SROW;

        const int wt   = tgt_l >> 6;
        const int slot = (tgt_l & 63) + 32;
        const bool mine = (warp == wt) && (lane == slot / 3);
        const int  msel = slot - 3 * (slot / 3);

        float a0 = 0.f, a1 = 0.f, a2 = 0.f;
        int   e0 = E_SENT, e1 = E_SENT, e2 = E_SENT;
        float f0 = 0.f, f1 = 0.f, f2 = 0.f;

#define SNAPVAL(AV, EV) ((AV) == 0.0f ? -1e30f : (f_lg2(AV) + (float)(EV)) * LN2)

#define STEP(BUFC, J, T)                                                  \
        {                                                                 \
            float p0 = (BUFC)[cr0 + (J)] + 1e-30f;                        \
            float p1 = (BUFC)[cr1 + (J)] + 1e-30f;                        \
            float p2 = (BUFC)[cr2 + (J)] + 1e-30f;                        \
            float sh = __shfl_up_sync(0xffffffffu, a2, 1);                \
            if (lane == 0) sh = 0.0f;                                     \
            float n0 = fmaf(a0, p0, sh * (f0 * p0));                      \
            float n1 = fmaf(a1, p1, a0 * (f1 * p1));                      \
            float n2 = fmaf(a2, p2, a1 * (f2 * p2));                      \
            a0 = n0; a1 = n1; a2 = n2;                                    \
            if (mine && (T) == tgt_t) {                                   \
                float av = (msel == 0) ? a0 : ((msel == 1) ? a1 : a2);    \
                int   ev = (msel == 0) ? e0 : ((msel == 1) ? e1 : e2);    \
                g_alpha_last[b] = SNAPVAL(av, ev);                        \
            }                                                             \
        }

        // Renormalize: mantissa-normalize, sentinel scale adoption via
        // "last real E before me" segmented scan, pairwise-max rebase, new f's.
#define RENORM()                                                          \
        {                                                                 \
            int bi, ex;                                                   \
            bi = __float_as_int(a0); ex = (bi >> 23) & 255;               \
            bool R0 = (ex != 0);                                          \
            if (R0) { e0 += ex - 127;                                     \
                      a0 = __int_as_float((bi & 0x807FFFFF) | 0x3F800000);}\
            else    { a0 = 0.f; e0 = E_SENT; }                            \
            bi = __float_as_int(a1); ex = (bi >> 23) & 255;               \
            bool R1 = (ex != 0);                                          \
            if (R1) { e1 += ex - 127;                                     \
                      a1 = __int_as_float((bi & 0x807FFFFF) | 0x3F800000);}\
            else    { a1 = 0.f; e1 = E_SENT; }                            \
            bi = __float_as_int(a2); ex = (bi >> 23) & 255;               \
            bool R2 = (ex != 0);                                          \
            if (R2) { e2 += ex - 127;                                     \
                      a2 = __int_as_float((bi & 0x807FFFFF) | 0x3F800000);}\
            else    { a2 = 0.f; e2 = E_SENT; }                            \
            /* lane-local last-real */                                    \
            int lv = R2 ? e2 : (R1 ? e1 : (R0 ? e0 : E_SENT));            \
            int lf = (int)(R0 | R1 | R2);                                 \
            _Pragma("unroll")                                             \
            for (int d = 1; d < 32; d <<= 1) {                            \
                int ov = __shfl_up_sync(0xffffffffu, lv, d);              \
                int of = __shfl_up_sync(0xffffffffu, lf, d);              \
                if (lane >= d && !lf) { lv = ov; lf = of; }               \
            }                                                             \
            int Lin = __shfl_up_sync(0xffffffffu, lv, 1);                 \
            if (lane == 0) Lin = E_SENT;                                  \
            int pl = __shfl_up_sync(0xffffffffu, e2, 1);                  \
            if (lane == 0) pl = E_SENT;                                   \
            int P0 = R0 ? ((e0 > pl) ? e0 : pl) : Lin;                    \
            int L1 = R0 ? e0 : Lin;                                       \
            int P1 = R1 ? ((e1 > e0) ? e1 : e0) : L1;                     \
            int L2 = R1 ? e1 : L1;                                        \
            int P2 = R2 ? ((e2 > e1) ? e2 : e1) : L2;                     \
            a0 *= pow2s(e0 - P0);                                         \
            a1 *= pow2s(e1 - P1);                                         \
            a2 *= pow2s(e2 - P2);                                         \
            int PL = __shfl_up_sync(0xffffffffu, P2, 1);                  \
            if (lane == 0) PL = E_SENT;                                   \
            f0 = pow2s(PL - P0);                                          \
            f1 = pow2s(P0 - P1);                                          \
            f2 = pow2s(P1 - P2);                                          \
            e0 = P0; e1 = P1; e2 = P2;                                    \
        }

#define HALO(C)                                                           \
        {                                                                 \
            const int s0 = 3 * lane;                                      \
            float* ha = &hA[(C) & 1][warp][0];                            \
            int*   he = &hE[(C) & 1][warp][0];                            \
            if (s0     >= 64) { ha[s0 - 64] = a0; he[s0 - 64] = e0; }     \
            if (s0 + 1 >= 64) { ha[s0 - 63] = a1; he[s0 - 63] = e1; }     \
            if (s0 + 2 >= 64) { ha[s0 - 62] = a2; he[s0 - 62] = e2; }     \
            asm volatile("bar.sync 1, 128;" ::: "memory");                \
            if (warp > 0) {                                               \
                const float* ra = &hA[(C) & 1][warp - 1][0];              \
                const int*   re = &hE[(C) & 1][warp - 1][0];              \
                if (s0     < 32) { a0 = ra[s0];     e0 = re[s0];     }    \
                if (s0 + 1 < 32) { a1 = ra[s0 + 1]; e1 = re[s0 + 1]; }    \
                if (s0 + 2 < 32) { a2 = ra[s0 + 2]; e2 = re[s0 + 2]; }    \
            }                                                             \
        }

        // ---- chunk 0 (t=0 is init, steps t=1..31) ----
        mbar_wait(FULL_A(0), 0);
        {
            const float* bufc = sbuf;
            if (warp == 0 && lane == 10) { a2 = bufc[0] + 1e-30f; e2 = 0; }
            if (tgt_t == 0 && mine) {
                float av = (msel == 0) ? a0 : ((msel == 1) ? a1 : a2);
                int   ev = (msel == 0) ? e0 : ((msel == 1) ? e1 : e2);
                g_alpha_last[b] = SNAPVAL(av, ev);
            }
            RENORM()
#pragma unroll
            for (int j = 1; j < 16; ++j) STEP(bufc, j, j)
            RENORM()
#pragma unroll
            for (int j = 16; j < 32; ++j) STEP(bufc, j, j)
        }
        if (lane == 0) mbar_arrive(EMPTY_A(0));
        HALO(0)

        // ---- chunks 1..49 ----
        for (int c = 1; c < NCH; ++c) {
            const int s = c & 3, u = c >> 2;
            mbar_wait(FULL_A(s), u & 1);
            const float* bufc = sbuf + s * BUF_FLOATS;
            const int tbase = c * TC;
            RENORM()
#pragma unroll
            for (int j = 0; j < 16; ++j) STEP(bufc, j, tbase + j)
            RENORM()
#pragma unroll
            for (int j = 16; j < 32; ++j) STEP(bufc, j, tbase + j)
            if (lane == 0) mbar_arrive(EMPTY_A(s));
            HALO(c)
        }
    }

    __syncthreads();

    // last block to finish computes loss = -mean(alpha_last)
    if (tid == 0) {
        __threadfence();
        unsigned old = atomicAdd(&g_done_ctr, 1u);
        if (old == BB - 1) {
            g_done_ctr = 0;                          // reset for graph replay
            __threadfence();
            float s = 0.0f;
#pragma unroll
            for (int i = 0; i < BB; ++i) s += g_alpha_last[i];
            out[0] = -s * (1.0f / BB);
        }
    }
}

// ---------------------------------------------------------------------------
// Elementwise kernel (forked stream): out[1+i] = log(probs[i] + 1e-30)
// ---------------------------------------------------------------------------
__global__ void k_elem(const float* __restrict__ probs,
                       float* __restrict__ mat,     // = out + 1
                       long long nvec)              // number of float4
{
    long long i = (long long)blockIdx.x * blockDim.x + threadIdx.x;
    long long stride = (long long)gridDim.x * blockDim.x;
    const float4* p4 = reinterpret_cast<const float4*>(probs);
    for (; i < nvec; i += stride) {
        float4 v = p4[i];
        long long o = i * 4;
        mat[o + 0] = __logf(v.x + 1e-30f);
        mat[o + 1] = __logf(v.y + 1e-30f);
        mat[o + 2] = __logf(v.z + 1e-30f);
        mat[o + 3] = __logf(v.w + 1e-30f);
    }
}

// ---------------------------------------------------------------------------
extern "C" void kernel_launch(void* const* d_in, const int* in_sizes, int n_in,
                              void* d_out, int out_size)
{
    const float* probs        = (const float*)d_in[0];
    // d_in[1] = melspec (unused by the computation)
    const int*   text_lengths = (const int*)d_in[2];
    const int*   mel_lengths  = (const int*)d_in[3];

    float* out = (float*)d_out;   // out[0] = loss, out[1..] = log matrix

    static cudaStream_t s2 = nullptr;
    static cudaEvent_t  evF = nullptr, evJ = nullptr;
    if (s2 == nullptr) {
        cudaStreamCreateWithFlags(&s2, cudaStreamNonBlocking);
        cudaEventCreateWithFlags(&evF, cudaEventDisableTiming);
        cudaEventCreateWithFlags(&evJ, cudaEventDisableTiming);
        cudaFuncSetAttribute(k_rec, cudaFuncAttributeMaxDynamicSharedMemorySize,
                             SMEM_BYTES);
    }

    const long long nvec = (long long)BB * LL * TT / 4;

    // fork: elementwise on s2, recursion on the main (capture) stream
    cudaEventRecord(evF, 0);
    cudaStreamWaitEvent(s2, evF, 0);
    k_elem<<<1184, 256, 0, s2>>>(probs, out + 1, nvec);
    cudaEventRecord(evJ, s2);

    k_rec<<<BB, 256, SMEM_BYTES, 0>>>(probs, text_lengths, mel_lengths, out);

    // join
    cudaStreamWaitEvent(0, evJ, 0);
    (void)in_sizes; (void)n_in; (void)out_size;
}

// round 11
// speedup vs baseline: 1.7150x; 1.0965x over previous
#include <cuda_runtime.h>
#include <cuda_bf16.h>
#include <cstdint>

// Problem shape (fixed by dataset)
#define BB 64
#define LL 256
#define TT 1600
#define TC 32                       // time-chunk (= halo width)
#define SROW 33                     // smem row stride (floats), conflict-free
#define NCH 50                      // TT / TC
#define NBUF 4                      // pipeline depth
#define BUF_FLOATS (LL * SROW)      // 8448
#define SMEM_BYTES (NBUF * BUF_FLOATS * 4)   // 135,168 B
#define LN2 0.69314718055994531f
#define E_SENT (-(1 << 26))         // exponent sentinel (int)

__device__ float g_alpha_last[BB];
__device__ unsigned int g_done_ctr = 0;

__device__ __forceinline__ float f_lg2(float x) {
    float r; asm("lg2.approx.f32 %0, %1;" : "=f"(r) : "f"(x)); return r;
}
// 2^k as float, clamped: k>126 -> 2^126, k<-126 -> 0
__device__ __forceinline__ float pow2s(int k) {
    k = (k > 126) ? 126 : k;
    return (k < -126) ? 0.0f : __int_as_float((k + 127) << 23);
}

__device__ __forceinline__ void mbar_init(uint32_t a, uint32_t cnt) {
    asm volatile("mbarrier.init.shared.b64 [%0], %1;" :: "r"(a), "r"(cnt) : "memory");
}
__device__ __forceinline__ void mbar_arrive(uint32_t a) {
    asm volatile("mbarrier.arrive.shared.b64 _, [%0];" :: "r"(a) : "memory");
}
__device__ __forceinline__ void mbar_wait(uint32_t a, uint32_t phase) {
    asm volatile(
        "{\n\t.reg .pred P;\n\t"
        "WL_%=:\n\t"
        "mbarrier.try_wait.parity.acquire.cta.shared::cta.b64 P, [%0], %1, 0x989680;\n\t"
        "@P bra.uni WD_%=;\n\t"
        "bra.uni WL_%=;\n\t"
        "WD_%=:\n\t}"
        :: "r"(a), "r"(phase) : "memory");
}

extern __shared__ float sbuf[];   // NBUF buffers of [LL][SROW], probs + 1e-30

// ---------------------------------------------------------------------------
// Recursion kernel: one block per batch, 256 threads.
//   warps 0-3 (recursion): halo layout (warp w carries labels [64w-32,64w+64),
//     3 slots/thread). Alpha in LINEAR domain as a*2^E (block floating point):
//     step = p*(a + left*f), 3 FMA + 3 MUL, no MUFU, no selects.
//     Renormalize every 16 steps (mantissa normalize + depth-24-slot exponent
//     adoption scan + pairwise rebase; f0 forced 0 on lane 0 = degradation
//     front). a == 0 represents the absorbed -1e30 sentinel exactly.
//   warps 4-7 (convert): LDG.128 raw probs -> +1e-30 -> STS.
// ---------------------------------------------------------------------------
__global__ void __launch_bounds__(256, 1)
k_rec(const float* __restrict__ probs,
      const int* __restrict__ text_lengths,
      const int* __restrict__ mel_lengths,
      float* __restrict__ out)
{
    __shared__ float hA[2][4][32];      // halo exchange: mantissas
    __shared__ int   hE[2][4][32];      // halo exchange: exponents
    __shared__ __align__(8) unsigned long long mbar_store[2 * NBUF];

    const int b    = blockIdx.x;
    const int tid  = threadIdx.x;
    const int warp = tid >> 5;
    const int lane = tid & 31;

    const int tgt_t = __ldg(mel_lengths  + b) - 1;
    const int tgt_l = __ldg(text_lengths + b) - 1;

    const float* pbase = probs + (size_t)b * LL * TT;

    const uint32_t mb = (uint32_t)__cvta_generic_to_shared(mbar_store);
#define FULL_A(s)  (mb + (uint32_t)(s) * 8u)
#define EMPTY_A(s) (mb + 32u + (uint32_t)(s) * 8u)

    if (tid == 0) {
#pragma unroll
        for (int s = 0; s < NBUF; ++s) {
            mbar_init(FULL_A(s), 4);    // one arrive per convert warp
            mbar_init(EMPTY_A(s), 4);   // one arrive per recursion warp
        }
    }
    __syncthreads();

    if (warp >= 4) {
        // ============== convert / producer (copy + 1e-30 floor) ============
        const int wtid = tid - 128;     // 0..127
        for (int c = 0; c < NCH; ++c) {
            const int s = c & 3, u = c >> 2;
            mbar_wait(EMPTY_A(s), (u & 1) ^ 1);
            float* buf = sbuf + s * BUF_FLOATS;
            const float* gsrc = pbase + c * TC;
#pragma unroll
            for (int k = 0; k < 16; ++k) {
                const int i   = wtid + k * 128;    // 0..2047
                const int row = i >> 3;
                const int c4  = (i & 7) * 4;
                const float4 v = *reinterpret_cast<const float4*>(
                                     gsrc + (size_t)row * TT + c4);
                float* sp = buf + row * SROW + c4;
                sp[0] = v.x + 1e-30f; sp[1] = v.y + 1e-30f;
                sp[2] = v.z + 1e-30f; sp[3] = v.w + 1e-30f;
            }
            if (lane == 0) mbar_arrive(FULL_A(s));
        }
    } else {
        // ======================= recursion / consumer ======================
        const int Wb = 64 * warp - 32;
        const int r0 = Wb + 3 * lane, r1 = r0 + 1, r2 = r0 + 2;
        const int cr0 = ((r0 >= 0) ? r0 : 0) * SROW;   // invalid slots keep a=0
        const int cr1 = ((r1 >= 0) ? r1 : 0) * SROW;
        const int cr2 = ((r2 >= 0) ? r2 : 0) * SROW;

        const int wt   = tgt_l >> 6;
        const int slot = (tgt_l & 63) + 32;
        const bool mine = (warp == wt) && (lane == slot / 3);
        const int  msel = slot - 3 * (slot / 3);

        float a0 = 0.f, a1 = 0.f, a2 = 0.f;
        int   e0 = E_SENT, e1 = E_SENT, e2 = E_SENT;
        float f0 = 0.f, f1 = 0.f, f2 = 0.f;

#define SNAPVAL(AV, EV) ((AV) == 0.0f ? -1e30f : (f_lg2(AV) + (float)(EV)) * LN2)

#define STEP(BUFC, J, T)                                                  \
        {                                                                 \
            float p0 = (BUFC)[cr0 + (J)];                                 \
            float p1 = (BUFC)[cr1 + (J)];                                 \
            float p2 = (BUFC)[cr2 + (J)];                                 \
            float sh = __shfl_up_sync(0xffffffffu, a2, 1);                \
            float t0 = fmaf(sh, f0, a0);     /* lane0: f0==0 */           \
            float t1 = fmaf(a0, f1, a1);                                  \
            float t2 = fmaf(a1, f2, a2);                                  \
            a0 = t0 * p0; a1 = t1 * p1; a2 = t2 * p2;                     \
            if (mine && (T) == tgt_t) {                                   \
                float av = (msel == 0) ? a0 : ((msel == 1) ? a1 : a2);    \
                int   ev = (msel == 0) ? e0 : ((msel == 1) ? e1 : e2);    \
                g_alpha_last[b] = SNAPVAL(av, ev);                        \
            }                                                             \
        }

        // Renormalize: mantissa-normalize, exponent adoption for dead slots
        // (depth-24-slot segmented scan, sufficient for 16-step mass reach),
        // pairwise-max rebase, new f's; f0 forced 0 on lane 0.
#define RENORM()                                                          \
        {                                                                 \
            int bi, ex;                                                   \
            bi = __float_as_int(a0); ex = (bi >> 23) & 255;               \
            bool R0 = (ex != 0);                                          \
            if (R0) { e0 += ex - 127;                                     \
                      a0 = __int_as_float((bi & 0x807FFFFF) | 0x3F800000);}\
            else    { a0 = 0.f; e0 = E_SENT; }                            \
            bi = __float_as_int(a1); ex = (bi >> 23) & 255;               \
            bool R1 = (ex != 0);                                          \
            if (R1) { e1 += ex - 127;                                     \
                      a1 = __int_as_float((bi & 0x807FFFFF) | 0x3F800000);}\
            else    { a1 = 0.f; e1 = E_SENT; }                            \
            bi = __float_as_int(a2); ex = (bi >> 23) & 255;               \
            bool R2 = (ex != 0);                                          \
            if (R2) { e2 += ex - 127;                                     \
                      a2 = __int_as_float((bi & 0x807FFFFF) | 0x3F800000);}\
            else    { a2 = 0.f; e2 = E_SENT; }                            \
            int lv = R2 ? e2 : (R1 ? e1 : (R0 ? e0 : E_SENT));            \
            int lf = (int)(R0 | R1 | R2);                                 \
            _Pragma("unroll")                                             \
            for (int d = 1; d < 8; d <<= 1) {                             \
                int ov = __shfl_up_sync(0xffffffffu, lv, d);              \
                int of = __shfl_up_sync(0xffffffffu, lf, d);              \
                if (lane >= d && !lf) { lv = ov; lf = of; }               \
            }                                                             \
            int Lin = __shfl_up_sync(0xffffffffu, lv, 1);                 \
            if (lane == 0) Lin = E_SENT;                                  \
            int pl = __shfl_up_sync(0xffffffffu, e2, 1);                  \
            if (lane == 0) pl = E_SENT;                                   \
            int P0 = R0 ? ((e0 > pl) ? e0 : pl) : Lin;                    \
            int L1 = R0 ? e0 : Lin;                                       \
            int P1 = R1 ? ((e1 > e0) ? e1 : e0) : L1;                     \
            int L2 = R1 ? e1 : L1;                                        \
            int P2 = R2 ? ((e2 > e1) ? e2 : e1) : L2;                     \
            a0 *= pow2s(e0 - P0);                                         \
            a1 *= pow2s(e1 - P1);                                         \
            a2 *= pow2s(e2 - P2);                                         \
            int PL = __shfl_up_sync(0xffffffffu, P2, 1);                  \
            if (lane == 0) PL = E_SENT;                                   \
            f0 = pow2s(PL - P0);                                          \
            if (lane == 0) f0 = 0.0f;   /* degradation front */           \
            f1 = pow2s(P0 - P1);                                          \
            f2 = pow2s(P1 - P2);                                          \
            e0 = P0; e1 = P1; e2 = P2;                                    \
        }

#define HALO(C)                                                           \
        {                                                                 \
            const int s0 = 3 * lane;                                      \
            float* ha = &hA[(C) & 1][warp][0];                            \
            int*   he = &hE[(C) & 1][warp][0];                            \
            if (s0     >= 64) { ha[s0 - 64] = a0; he[s0 - 64] = e0; }     \
            if (s0 + 1 >= 64) { ha[s0 - 63] = a1; he[s0 - 63] = e1; }     \
            if (s0 + 2 >= 64) { ha[s0 - 62] = a2; he[s0 - 62] = e2; }     \
            asm volatile("bar.sync 1, 128;" ::: "memory");                \
            if (warp > 0) {                                               \
                const float* ra = &hA[(C) & 1][warp - 1][0];              \
                const int*   re = &hE[(C) & 1][warp - 1][0];              \
                if (s0     < 32) { a0 = ra[s0];     e0 = re[s0];     }    \
                if (s0 + 1 < 32) { a1 = ra[s0 + 1]; e1 = re[s0 + 1]; }    \
                if (s0 + 2 < 32) { a2 = ra[s0 + 2]; e2 = re[s0 + 2]; }    \
            }                                                             \
        }

        // ---- chunk 0 (t=0 is init, steps t=1..31) ----
        mbar_wait(FULL_A(0), 0);
        {
            const float* bufc = sbuf;
            if (warp == 0 && lane == 10) { a2 = bufc[0]; e2 = 0; }  // pre-floored
            if (tgt_t == 0 && mine) {
                float av = (msel == 0) ? a0 : ((msel == 1) ? a1 : a2);
                int   ev = (msel == 0) ? e0 : ((msel == 1) ? e1 : e2);
                g_alpha_last[b] = SNAPVAL(av, ev);
            }
            RENORM()
#pragma unroll
            for (int j = 1; j < 16; ++j) STEP(bufc, j, j)
            RENORM()
#pragma unroll
            for (int j = 16; j < 32; ++j) STEP(bufc, j, j)
        }
        if (lane == 0) mbar_arrive(EMPTY_A(0));
        HALO(0)

        // ---- chunks 1..49 ----
        for (int c = 1; c < NCH; ++c) {
            const int s = c & 3, u = c >> 2;
            mbar_wait(FULL_A(s), u & 1);
            const float* bufc = sbuf + s * BUF_FLOATS;
            const int tbase = c * TC;
            RENORM()
#pragma unroll
            for (int j = 0; j < 16; ++j) STEP(bufc, j, tbase + j)
            RENORM()
#pragma unroll
            for (int j = 16; j < 32; ++j) STEP(bufc, j, tbase + j)
            if (lane == 0) mbar_arrive(EMPTY_A(s));
            HALO(c)
        }
    }

    __syncthreads();

    // last block to finish computes loss = -mean(alpha_last)
    if (tid == 0) {
        __threadfence();
        unsigned old = atomicAdd(&g_done_ctr, 1u);
        if (old == BB - 1) {
            g_done_ctr = 0;                          // reset for graph replay
            __threadfence();
            float s = 0.0f;
#pragma unroll
            for (int i = 0; i < BB; ++i) s += g_alpha_last[i];
            out[0] = -s * (1.0f / BB);
        }
    }
}

// ---------------------------------------------------------------------------
// Elementwise kernel (forked stream): out[1+i] = log(probs[i] + 1e-30)
// ---------------------------------------------------------------------------
__global__ void k_elem(const float* __restrict__ probs,
                       float* __restrict__ mat,     // = out + 1
                       long long nvec)              // number of float4
{
    long long i = (long long)blockIdx.x * blockDim.x + threadIdx.x;
    long long stride = (long long)gridDim.x * blockDim.x;
    const float4* p4 = reinterpret_cast<const float4*>(probs);
    for (; i < nvec; i += stride) {
        float4 v = p4[i];
        long long o = i * 4;
        mat[o + 0] = __logf(v.x + 1e-30f);
        mat[o + 1] = __logf(v.y + 1e-30f);
        mat[o + 2] = __logf(v.z + 1e-30f);
        mat[o + 3] = __logf(v.w + 1e-30f);
    }
}

// ---------------------------------------------------------------------------
extern "C" void kernel_launch(void* const* d_in, const int* in_sizes, int n_in,
                              void* d_out, int out_size)
{
    const float* probs        = (const float*)d_in[0];
    // d_in[1] = melspec (unused by the computation)
    const int*   text_lengths = (const int*)d_in[2];
    const int*   mel_lengths  = (const int*)d_in[3];

    float* out = (float*)d_out;   // out[0] = loss, out[1..] = log matrix

    static cudaStream_t s2 = nullptr;
    static cudaEvent_t  evF = nullptr, evJ = nullptr;
    if (s2 == nullptr) {
        cudaStreamCreateWithFlags(&s2, cudaStreamNonBlocking);
        cudaEventCreateWithFlags(&evF, cudaEventDisableTiming);
        cudaEventCreateWithFlags(&evJ, cudaEventDisableTiming);
        cudaFuncSetAttribute(k_rec, cudaFuncAttributeMaxDynamicSharedMemorySize,
                             SMEM_BYTES);
    }

    const long long nvec = (long long)BB * LL * TT / 4;

    // fork: elementwise on s2, recursion on the main (capture) stream
    cudaEventRecord(evF, 0);
    cudaStreamWaitEvent(s2, evF, 0);
    k_elem<<<1184, 256, 0, s2>>>(probs, out + 1, nvec);
    cudaEventRecord(evJ, s2);

    k_rec<<<BB, 256, SMEM_BYTES, 0>>>(probs, text_lengths, mel_lengths, out);

    // join
    cudaStreamWaitEvent(0, evJ, 0);
    (void)in_sizes; (void)n_in; (void)out_size;
}